// round 1
// baseline (speedup 1.0000x reference)
#include <cuda_runtime.h>
#include <cuda_bf16.h>
#include <math.h>
#include <stdint.h>

// Problem constants
#define NB_  32      // batch
#define NH_  64      // heads
#define ND_  512     // head dim
#define NROPE_ 64
#define NHALF_ 32
#define SMAX_ 4096
#define MB_  64      // blocks per batch in table
#define BS_  64      // page size
#define IH_  64
#define ID_  128
#define TOPK_ 512
#define SCALE_ 0.04419417382415922f  // 1/sqrt(512)

// ---------------- scratch (device globals; no allocation) ----------------
__device__ float    g_qr[NB_*NH_*ND_];        // rotated q (4MB)
__device__ unsigned g_qq[NB_*IH_*32];         // packed int8 q_idx (32 words/row)
__device__ float    g_qs[NB_*IH_];            // q_idx scales
__device__ float    g_iscore[NB_*SMAX_];      // indexer scores
__device__ int      g_sel[NB_*(TOPK_+1)];     // selected s indices per batch
__device__ int      g_nsel[NB_];              // count (512 or 513)

// ---------------- kernel 1: partial rotary on q ----------------
__global__ void rope_kernel(const float* __restrict__ q,
                            const float* __restrict__ cosp,
                            const float* __restrict__ sinp) {
    int bh = blockIdx.x;            // 0..2047
    int b  = bh >> 6;
    int d  = threadIdx.x * 4;       // 128 threads
    const float* src = q + (size_t)bh * ND_;
    float4 v = *(const float4*)(src + d);
    float4 o;
    if (d < ND_ - NROPE_) {
        o = v;
    } else {
        int i0 = (d - (ND_ - NROPE_)) >> 1;   // pair index for (x,y)
        float c0 = cosp[b*NHALF_ + i0],   s0 = sinp[b*NHALF_ + i0];
        float c1 = cosp[b*NHALF_ + i0+1], s1 = sinp[b*NHALF_ + i0+1];
        o.x = v.x*c0 - v.y*s0;
        o.y = v.x*s0 + v.y*c0;
        o.z = v.z*c1 - v.w*s1;
        o.w = v.z*s1 + v.w*c1;
    }
    *(float4*)(g_qr + (size_t)bh*ND_ + d) = o;
}

// ---------------- helpers ----------------
__device__ __forceinline__ int quant1(float x, float scale) {
    float r = rintf(x / scale);                 // true divide to match jnp
    r = fminf(fmaxf(r, -128.f), 127.f);
    return (int)r;
}

// ---------------- kernel 2: quantize q_idx ----------------
__global__ void qquant_kernel(const float* __restrict__ q_idx) {
    int row  = blockIdx.x * 8 + (threadIdx.x >> 5);   // B*IH = 2048 rows
    int lane = threadIdx.x & 31;
    float4 v = *(const float4*)(q_idx + (size_t)row*ID_ + lane*4);
    float m = fmaxf(fmaxf(fabsf(v.x), fabsf(v.y)), fmaxf(fabsf(v.z), fabsf(v.w)));
    #pragma unroll
    for (int o = 16; o; o >>= 1) m = fmaxf(m, __shfl_xor_sync(0xffffffffu, m, o));
    float scale = fmaxf(m, 1e-12f) * (1.f/127.f);
    if (scale < 1e-6f) scale = 1.f;
    int q0 = quant1(v.x, scale), q1 = quant1(v.y, scale);
    int q2 = quant1(v.z, scale), q3 = quant1(v.w, scale);
    unsigned w = (q0 & 0xFF) | ((q1 & 0xFF) << 8) | ((q2 & 0xFF) << 16) | ((q3 & 0xFF) << 24);
    g_qq[row*32 + lane] = w;
    if (lane == 0) g_qs[row] = scale;
}

// ---------------- kernel 3: indexer scores ----------------
// grid (16 chunks, 32 batches), 256 threads. Warp per key position s.
__global__ void indexer_kernel(const float* __restrict__ k_idx_cache,
                               const int* __restrict__ btbl,
                               const int* __restrict__ seq_lens) {
    __shared__ unsigned sqq[IH_*33];   // padded rows -> conflict-free
    __shared__ float    sqs[IH_];
    int b = blockIdx.y, chunk = blockIdx.x;
    for (int i = threadIdx.x; i < IH_*32; i += 256) {
        int h = i >> 5, w = i & 31;
        sqq[h*33 + w] = g_qq[b*IH_*32 + i];
    }
    if (threadIdx.x < IH_) sqs[threadIdx.x] = g_qs[b*IH_ + threadIdx.x];
    __syncthreads();

    int lane = threadIdx.x & 31, wrp = threadIdx.x >> 5;
    int seqlen = seq_lens[b];
    float negInf = __int_as_float(0xff800000);

    for (int i = 0; i < 32; i++) {
        int s = chunk*256 + i*8 + wrp;
        if (s >= seqlen) {
            if (lane == 0) g_iscore[b*SMAX_ + s] = negInf;
            continue;
        }
        int pg = btbl[(b << 6) + (s >> 6)];
        const float* kr = k_idx_cache + ((size_t)pg*BS_ + (s & 63)) * ID_;
        float4 v = *(const float4*)(kr + lane*4);
        float m = fmaxf(fmaxf(fabsf(v.x), fabsf(v.y)), fmaxf(fabsf(v.z), fabsf(v.w)));
        #pragma unroll
        for (int o = 16; o; o >>= 1) m = fmaxf(m, __shfl_xor_sync(0xffffffffu, m, o));
        float scale = fmaxf(m, 1e-12f) * (1.f/127.f);
        if (scale < 1e-6f) scale = 1.f;
        int q0 = quant1(v.x, scale), q1 = quant1(v.y, scale);
        int q2 = quant1(v.z, scale), q3 = quant1(v.w, scale);
        unsigned kw = (q0 & 0xFF) | ((q1 & 0xFF) << 8) | ((q2 & 0xFF) << 16) | ((q3 & 0xFF) << 24);

        int acc0 = 0, acc1 = 0;
        const unsigned* qh0 = sqq + lane*33;
        const unsigned* qh1 = sqq + (lane+32)*33;
        #pragma unroll
        for (int w = 0; w < 32; w++) {
            unsigned kk = __shfl_sync(0xffffffffu, kw, w);
            acc0 = __dp4a((int)qh0[w], (int)kk, acc0);
            acc1 = __dp4a((int)qh1[w], (int)kk, acc1);
        }
        float vsum = (float)acc0 * sqs[lane] + (float)acc1 * sqs[lane+32];
        #pragma unroll
        for (int o = 16; o; o >>= 1) vsum += __shfl_xor_sync(0xffffffffu, vsum, o);
        if (lane == 0) g_iscore[b*SMAX_ + s] = vsum * scale;
    }
}

// ---------------- kernel 4: exact top-k (radix select) ----------------
__device__ __forceinline__ int block_exscan256(int v, int* sh, int* total) {
    int t = threadIdx.x, lane = t & 31, wid = t >> 5;
    __syncthreads();               // protect shared reuse
    int incl = v;
    #pragma unroll
    for (int o = 1; o < 32; o <<= 1) {
        int n = __shfl_up_sync(0xffffffffu, incl, o);
        if (lane >= o) incl += n;
    }
    if (lane == 31) sh[wid] = incl;
    __syncthreads();
    if (wid == 0) {
        int x = (lane < 8) ? sh[lane] : 0;
        #pragma unroll
        for (int o = 1; o < 8; o <<= 1) {
            int n = __shfl_up_sync(0xffffffffu, x, o);
            if (lane >= o) x += n;
        }
        if (lane < 8) sh[lane] = x;
    }
    __syncthreads();
    int base = wid ? sh[wid-1] : 0;
    *total = sh[7];
    return base + incl - v;    // exclusive
}

__global__ void topk_kernel() {
    int b = blockIdx.x;
    __shared__ unsigned skey[SMAX_];
    __shared__ unsigned hist[256];
    __shared__ int sscan[9];
    __shared__ unsigned sinfo[2];
    int t = threadIdx.x;   // 256 threads

    for (int i = t; i < SMAX_; i += 256) {
        unsigned u = __float_as_uint(g_iscore[b*SMAX_ + i]);
        skey[i] = (u & 0x80000000u) ? ~u : (u | 0x80000000u);
    }
    __syncthreads();

    unsigned prefix = 0, mask = 0;
    int Krem = TOPK_;
    for (int shift = 24; shift >= 0; shift -= 8) {
        hist[t] = 0;
        __syncthreads();
        for (int i = t; i < SMAX_; i += 256) {
            unsigned u = skey[i];
            if ((u & mask) == prefix) atomicAdd(&hist[(u >> shift) & 255], 1u);
        }
        __syncthreads();
        if (t == 0) {
            int k = Krem, bin = 255;
            for (; bin >= 0; bin--) {
                int c = (int)hist[bin];
                if (k <= c) break;
                k -= c;
            }
            sinfo[0] = (unsigned)bin;
            sinfo[1] = (unsigned)k;
        }
        __syncthreads();
        prefix |= sinfo[0] << shift;
        mask   |= 0xFFu << shift;
        Krem = (int)sinfo[1];
        __syncthreads();
    }
    unsigned T = prefix;
    int R = Krem;   // number of ==T elements to keep (smallest indices first)

    // stable flags + compaction; thread t owns elements [16t, 16t+16)
    int base = t * 16;
    int eqc = 0;
    #pragma unroll
    for (int i = 0; i < 16; i++) eqc += (skey[base+i] == T);
    int tot;
    int eqoff = block_exscan256(eqc, sscan, &tot);

    int kc = 0;
    unsigned kmask = 0;
    int er = eqoff;
    #pragma unroll
    for (int i = 0; i < 16; i++) {
        unsigned u = skey[base+i];
        bool eq = (u == T);
        bool kp = (u > T) || (eq && er < R);
        er += eq;
        if (base + i == 0) kp = true;   // s=0 always kept
        kmask |= (unsigned)kp << i;
        kc += kp;
    }
    int koff = block_exscan256(kc, sscan, &tot);
    int p = koff;
    #pragma unroll
    for (int i = 0; i < 16; i++) {
        if ((kmask >> i) & 1) g_sel[b*(TOPK_+1) + p++] = base + i;
    }
    if (t == 0) g_nsel[b] = tot;
}

// ---------------- kernel 5: attention over selected keys ----------------
struct AttnSmem {
    float q[16][ND_];       // 32 KB
    float k[64][132];       // 33.8 KB, padded rows (conflict-free LDS.128)
    float sc[16][516];      // 33 KB scores / probs
    float inv[16];
};

__device__ __forceinline__ void load_ktile(float (*sk)[132],
                                           const float* __restrict__ kv,
                                           const int* __restrict__ btbl,
                                           int b, int kbase, int ch, int nsel, int t) {
    int r = t >> 2, part = t & 3;
    int j = kbase + r;
    if (j < nsel) {
        int sp = g_sel[b*(TOPK_+1) + j];
        int pg = btbl[(b << 6) + (sp >> 6)];
        const float* kr = kv + ((size_t)pg*BS_ + (sp & 63)) * ND_ + ch*128 + part*4;
        #pragma unroll
        for (int i = 0; i < 8; i++)
            *(float4*)&sk[r][part*4 + i*16] = *(const float4*)(kr + i*16);
    } else {
        float4 z = make_float4(0.f, 0.f, 0.f, 0.f);
        #pragma unroll
        for (int i = 0; i < 8; i++)
            *(float4*)&sk[r][part*4 + i*16] = z;
    }
}

extern __shared__ char smem_raw[];

__global__ void attn_kernel(const float* __restrict__ kv,
                            const float* __restrict__ attn_sink,
                            const int* __restrict__ btbl,
                            float* __restrict__ out) {
    AttnSmem& S = *(AttnSmem*)smem_raw;
    int b = blockIdx.y, hg = blockIdx.x;          // 4 groups of 16 heads
    int t = threadIdx.x;
    int nsel = g_nsel[b];
    int hbase = hg * 16;

    // load 16 q rows (contiguous 8192 floats)
    const float* qr = g_qr + ((size_t)b*NH_ + hbase) * ND_;
    for (int i = t*4; i < 16*ND_; i += 1024)
        *(float4*)&S.q[0][i] = *(const float4*)(qr + i);
    __syncthreads();

    int ht = t >> 5;       // head pair id: heads 2ht, 2ht+1 (warp-uniform)
    int jt = t & 31;       // key lane: keys jt, jt+32 of tile
    float snk0 = attn_sink[hbase + 2*ht];
    float snk1 = attn_sink[hbase + 2*ht + 1];

    int ntile = (nsel + 63) >> 6;

    // ---- phase A: scores ----
    for (int tt = 0; tt < ntile; tt++) {
        int kbase = tt * 64;
        float a00 = 0.f, a01 = 0.f, a10 = 0.f, a11 = 0.f;
        for (int ch = 0; ch < 4; ch++) {
            load_ktile(S.k, kv, btbl, b, kbase, ch, nsel, t);
            __syncthreads();
            const float* q0 = S.q[2*ht]   + ch*128;
            const float* q1 = S.q[2*ht+1] + ch*128;
            const float* k0 = S.k[jt];
            const float* k1 = S.k[jt+32];
            #pragma unroll 8
            for (int d = 0; d < 128; d += 4) {
                float4 kv0 = *(const float4*)(k0 + d);
                float4 kv1 = *(const float4*)(k1 + d);
                float4 qv0 = *(const float4*)(q0 + d);
                float4 qv1 = *(const float4*)(q1 + d);
                a00 = fmaf(qv0.x, kv0.x, a00); a00 = fmaf(qv0.y, kv0.y, a00);
                a00 = fmaf(qv0.z, kv0.z, a00); a00 = fmaf(qv0.w, kv0.w, a00);
                a01 = fmaf(qv0.x, kv1.x, a01); a01 = fmaf(qv0.y, kv1.y, a01);
                a01 = fmaf(qv0.z, kv1.z, a01); a01 = fmaf(qv0.w, kv1.w, a01);
                a10 = fmaf(qv1.x, kv0.x, a10); a10 = fmaf(qv1.y, kv0.y, a10);
                a10 = fmaf(qv1.z, kv0.z, a10); a10 = fmaf(qv1.w, kv0.w, a10);
                a11 = fmaf(qv1.x, kv1.x, a11); a11 = fmaf(qv1.y, kv1.y, a11);
                a11 = fmaf(qv1.z, kv1.z, a11); a11 = fmaf(qv1.w, kv1.w, a11);
            }
            __syncthreads();
        }
        int j0 = kbase + jt, j1 = j0 + 32;
        if (j0 < nsel) {
            bool z0 = (g_sel[b*(TOPK_+1) + j0] == 0);
            S.sc[2*ht][j0]   = a00 * SCALE_ + (z0 ? snk0 : 0.f);
            S.sc[2*ht+1][j0] = a10 * SCALE_ + (z0 ? snk1 : 0.f);
        }
        if (j1 < nsel) {
            bool z1 = (g_sel[b*(TOPK_+1) + j1] == 0);
            S.sc[2*ht][j1]   = a01 * SCALE_ + (z1 ? snk0 : 0.f);
            S.sc[2*ht+1][j1] = a11 * SCALE_ + (z1 ? snk1 : 0.f);
        }
    }
    __syncthreads();

    // ---- phase B: softmax (warp handles its 2 heads) ----
    #pragma unroll
    for (int hh = 0; hh < 2; hh++) {
        int hloc = 2*ht + hh;
        float m = -3.4e38f;
        for (int j = jt; j < nsel; j += 32) m = fmaxf(m, S.sc[hloc][j]);
        #pragma unroll
        for (int o = 16; o; o >>= 1) m = fmaxf(m, __shfl_xor_sync(0xffffffffu, m, o));
        float sum = 0.f;
        for (int j = jt; j < nsel; j += 32) {
            float e = expf(S.sc[hloc][j] - m);
            S.sc[hloc][j] = e;
            sum += e;
        }
        #pragma unroll
        for (int o = 16; o; o >>= 1) sum += __shfl_xor_sync(0xffffffffu, sum, o);
        if (jt == 0) S.inv[hloc] = 1.f / sum;
    }
    __syncthreads();

    // ---- phase C: weighted sum ----
    // thread: head pair 2ht,2ht+1 ; d = ch*128 + jt*4 .. +3
    for (int ch = 0; ch < 4; ch++) {
        float4 acc0 = make_float4(0.f,0.f,0.f,0.f);
        float4 acc1 = make_float4(0.f,0.f,0.f,0.f);
        for (int tt = 0; tt < ntile; tt++) {
            int kbase = tt * 64;
            load_ktile(S.k, kv, btbl, b, kbase, ch, nsel, t);
            __syncthreads();
            int jmax = nsel - kbase; if (jmax > 64) jmax = 64;
            const float* p0 = S.sc[2*ht]   + kbase;
            const float* p1 = S.sc[2*ht+1] + kbase;
            for (int j = 0; j < jmax; j++) {
                float w0 = p0[j], w1 = p1[j];
                float4 kvv = *(const float4*)&S.k[j][jt*4];
                acc0.x = fmaf(w0, kvv.x, acc0.x); acc0.y = fmaf(w0, kvv.y, acc0.y);
                acc0.z = fmaf(w0, kvv.z, acc0.z); acc0.w = fmaf(w0, kvv.w, acc0.w);
                acc1.x = fmaf(w1, kvv.x, acc1.x); acc1.y = fmaf(w1, kvv.y, acc1.y);
                acc1.z = fmaf(w1, kvv.z, acc1.z); acc1.w = fmaf(w1, kvv.w, acc1.w);
            }
            __syncthreads();
        }
        float i0 = S.inv[2*ht], i1 = S.inv[2*ht+1];
        float4 o0 = make_float4(acc0.x*i0, acc0.y*i0, acc0.z*i0, acc0.w*i0);
        float4 o1 = make_float4(acc1.x*i1, acc1.y*i1, acc1.z*i1, acc1.w*i1);
        size_t base0 = ((size_t)b*NH_ + hbase + 2*ht) * ND_ + ch*128 + jt*4;
        *(float4*)(out + base0)        = o0;
        *(float4*)(out + base0 + ND_)  = o1;
    }
}

// ---------------- launch ----------------
extern "C" void kernel_launch(void* const* d_in, const int* in_sizes, int n_in,
                              void* d_out, int out_size) {
    const float* q      = (const float*)d_in[0];
    const float* cosp   = (const float*)d_in[1];
    const float* sinp   = (const float*)d_in[2];
    const float* kv     = (const float*)d_in[3];
    const float* q_idx  = (const float*)d_in[4];
    const float* k_idx  = (const float*)d_in[5];
    const float* sink   = (const float*)d_in[6];
    const int*   btbl   = (const int*)d_in[7];
    const int*   slens  = (const int*)d_in[8];
    float* out = (float*)d_out;

    rope_kernel<<<NB_*NH_, 128>>>(q, cosp, sinp);
    qquant_kernel<<<NB_*IH_/8, 256>>>(q_idx);
    indexer_kernel<<<dim3(16, NB_), 256>>>(k_idx, btbl, slens);
    topk_kernel<<<NB_, 256>>>();

    int smem = (int)sizeof(AttnSmem);
    cudaFuncSetAttribute(attn_kernel, cudaFuncAttributeMaxDynamicSharedMemorySize, smem);
    attn_kernel<<<dim3(4, NB_), 256, smem>>>(kv, sink, btbl, out);
}

// round 2
// speedup vs baseline: 1.4303x; 1.4303x over previous
#include <cuda_runtime.h>
#include <cuda_bf16.h>
#include <math.h>
#include <stdint.h>

#define NB_  32
#define NH_  64
#define ND_  512
#define NROPE_ 64
#define NHALF_ 32
#define SMAX_ 4096
#define BS_  64
#define IH_  64
#define ID_  128
#define TOPK_ 512
#define SCALE_ 0.04419417382415922f

typedef unsigned long long ull;

// ---------------- scratch ----------------
__device__ float    g_qr[NB_*NH_*ND_];
__device__ unsigned g_qq[NB_*IH_*32];
__device__ float    g_qs[NB_*IH_];
__device__ float    g_iscore[NB_*SMAX_];
__device__ int      g_sel[NB_*(TOPK_+1)];
__device__ int      g_nsel[NB_];

// ---------------- f32x2 helpers ----------------
#define FMA2(d, a, b, c) asm("fma.rn.f32x2 %0, %1, %2, %3;" : "=l"(d) : "l"(a), "l"(b), "l"(c))
__device__ __forceinline__ ull dup2(float x){ ull r; asm("mov.b64 %0, {%1, %1};" : "=l"(r) : "f"(x)); return r; }
__device__ __forceinline__ float2 unpack2(ull v){ float2 r; asm("mov.b64 {%0, %1}, %2;" : "=f"(r.x), "=f"(r.y) : "l"(v)); return r; }

// ---------------- cp.async helpers ----------------
__device__ __forceinline__ void cpa16(void* dst_s, const void* src, int sz) {
    unsigned ds = (unsigned)__cvta_generic_to_shared(dst_s);
    asm volatile("cp.async.cg.shared.global [%0], [%1], 16, %2;" :: "r"(ds), "l"(src), "r"(sz));
}
#define CP_COMMIT() asm volatile("cp.async.commit_group;")
#define CP_WAIT1()  asm volatile("cp.async.wait_group 1;")
#define CP_WAIT0()  asm volatile("cp.async.wait_group 0;")

// ---------------- kernel 1: fused rope + q_idx quant ----------------
__device__ __forceinline__ int quant1(float x, float scale) {
    float r = rintf(x / scale);
    r = fminf(fmaxf(r, -128.f), 127.f);
    return (int)r;
}

__global__ void prep_kernel(const float* __restrict__ q,
                            const float* __restrict__ cosp,
                            const float* __restrict__ sinp,
                            const float* __restrict__ q_idx) {
    int t = threadIdx.x;
    if (blockIdx.x < 1024) {
        // rope: 2 (b,h) rows per block
        int bh = blockIdx.x * 2 + (t >> 7);
        int b  = bh >> 6;
        int d  = (t & 127) * 4;
        const float* src = q + (size_t)bh * ND_;
        float4 v = *(const float4*)(src + d);
        float4 o;
        if (d < ND_ - NROPE_) {
            o = v;
        } else {
            int i0 = (d - (ND_ - NROPE_)) >> 1;
            float c0 = cosp[b*NHALF_ + i0],   s0 = sinp[b*NHALF_ + i0];
            float c1 = cosp[b*NHALF_ + i0+1], s1 = sinp[b*NHALF_ + i0+1];
            o.x = v.x*c0 - v.y*s0;
            o.y = v.x*s0 + v.y*c0;
            o.z = v.z*c1 - v.w*s1;
            o.w = v.z*s1 + v.w*c1;
        }
        *(float4*)(g_qr + (size_t)bh*ND_ + d) = o;
    } else {
        // qquant: 8 rows per block
        int row  = (blockIdx.x - 1024) * 8 + (t >> 5);
        int lane = t & 31;
        float4 v = *(const float4*)(q_idx + (size_t)row*ID_ + lane*4);
        float m = fmaxf(fmaxf(fabsf(v.x), fabsf(v.y)), fmaxf(fabsf(v.z), fabsf(v.w)));
        #pragma unroll
        for (int o = 16; o; o >>= 1) m = fmaxf(m, __shfl_xor_sync(0xffffffffu, m, o));
        float scale = fmaxf(m, 1e-12f) * (1.f/127.f);
        if (scale < 1e-6f) scale = 1.f;
        int q0 = quant1(v.x, scale), q1 = quant1(v.y, scale);
        int q2 = quant1(v.z, scale), q3 = quant1(v.w, scale);
        unsigned w = (q0 & 0xFF) | ((q1 & 0xFF) << 8) | ((q2 & 0xFF) << 16) | ((q3 & 0xFF) << 24);
        g_qq[row*32 + lane] = w;
        if (lane == 0) g_qs[row] = scale;
    }
}

// ---------------- kernel 2: indexer scores ----------------
__global__ void indexer_kernel(const float* __restrict__ k_idx_cache,
                               const int* __restrict__ btbl,
                               const int* __restrict__ seq_lens) {
    __shared__ unsigned sqq[IH_*33];
    __shared__ float    sqs[IH_];
    int b = blockIdx.y, chunk = blockIdx.x;
    for (int i = threadIdx.x; i < IH_*32; i += 256) {
        int h = i >> 5, w = i & 31;
        sqq[h*33 + w] = g_qq[b*IH_*32 + i];
    }
    if (threadIdx.x < IH_) sqs[threadIdx.x] = g_qs[b*IH_ + threadIdx.x];
    __syncthreads();

    int lane = threadIdx.x & 31, wrp = threadIdx.x >> 5;
    int seqlen = seq_lens[b];
    float negInf = __int_as_float(0xff800000);

    for (int i = 0; i < 32; i++) {
        int s = chunk*256 + i*8 + wrp;
        if (s >= seqlen) {
            if (lane == 0) g_iscore[b*SMAX_ + s] = negInf;
            continue;
        }
        int pg = btbl[(b << 6) + (s >> 6)];
        const float* kr = k_idx_cache + ((size_t)pg*BS_ + (s & 63)) * ID_;
        float4 v = *(const float4*)(kr + lane*4);
        float m = fmaxf(fmaxf(fabsf(v.x), fabsf(v.y)), fmaxf(fabsf(v.z), fabsf(v.w)));
        #pragma unroll
        for (int o = 16; o; o >>= 1) m = fmaxf(m, __shfl_xor_sync(0xffffffffu, m, o));
        float scale = fmaxf(m, 1e-12f) * (1.f/127.f);
        if (scale < 1e-6f) scale = 1.f;
        int q0 = quant1(v.x, scale), q1 = quant1(v.y, scale);
        int q2 = quant1(v.z, scale), q3 = quant1(v.w, scale);
        unsigned kw = (q0 & 0xFF) | ((q1 & 0xFF) << 8) | ((q2 & 0xFF) << 16) | ((q3 & 0xFF) << 24);

        int acc0 = 0, acc1 = 0;
        const unsigned* qh0 = sqq + lane*33;
        const unsigned* qh1 = sqq + (lane+32)*33;
        #pragma unroll
        for (int w = 0; w < 32; w++) {
            unsigned kk = __shfl_sync(0xffffffffu, kw, w);
            acc0 = __dp4a((int)qh0[w], (int)kk, acc0);
            acc1 = __dp4a((int)qh1[w], (int)kk, acc1);
        }
        float vsum = (float)acc0 * sqs[lane] + (float)acc1 * sqs[lane+32];
        #pragma unroll
        for (int o = 16; o; o >>= 1) vsum += __shfl_xor_sync(0xffffffffu, vsum, o);
        if (lane == 0) g_iscore[b*SMAX_ + s] = vsum * scale;
    }
}

// ---------------- kernel 3: exact top-k, 512 threads ----------------
__device__ __forceinline__ int exscan512(int v, int* sh, int* total) {
    int t = threadIdx.x, lane = t & 31, wid = t >> 5;
    __syncthreads();
    int incl = v;
    #pragma unroll
    for (int o = 1; o < 32; o <<= 1) {
        int n = __shfl_up_sync(0xffffffffu, incl, o);
        if (lane >= o) incl += n;
    }
    if (lane == 31) sh[wid] = incl;
    __syncthreads();
    if (wid == 0) {
        int x = (lane < 16) ? sh[lane] : 0;
        #pragma unroll
        for (int o = 1; o < 16; o <<= 1) {
            int n = __shfl_up_sync(0xffffffffu, x, o);
            if (lane >= o) x += n;
        }
        if (lane < 16) sh[lane] = x;
    }
    __syncthreads();
    int base = wid ? sh[wid-1] : 0;
    *total = sh[15];
    return base + incl - v;
}

__global__ void topk_kernel() {
    int b = blockIdx.x;
    __shared__ unsigned skey[SMAX_];
    __shared__ int hist[256];
    __shared__ int sscan[17];
    __shared__ int sinfo[2];
    __shared__ int stot;
    int t = threadIdx.x;   // 512 threads
    int lane = t & 31, wid = t >> 5;

    for (int i = t; i < SMAX_; i += 512) {
        unsigned u = __float_as_uint(g_iscore[b*SMAX_ + i]);
        skey[i] = (u & 0x80000000u) ? ~u : (u | 0x80000000u);
    }
    __syncthreads();

    unsigned prefix = 0, mask = 0;
    int Krem = TOPK_;
    for (int shift = 24; shift >= 0; shift -= 8) {
        if (t < 256) hist[t] = 0;
        __syncthreads();
        for (int i = t; i < SMAX_; i += 512) {
            unsigned u = skey[i];
            if ((u & mask) == prefix) atomicAdd((unsigned*)&hist[(u >> shift) & 255], 1u);
        }
        __syncthreads();
        // parallel inclusive scan of 256 bins (threads 0..255, 8 warps)
        int c = (t < 256) ? hist[t] : 0;
        int incl = c;
        #pragma unroll
        for (int o = 1; o < 32; o <<= 1) {
            int n = __shfl_up_sync(0xffffffffu, incl, o);
            if (lane >= o) incl += n;
        }
        if (lane == 31 && wid < 8) sscan[wid] = incl;
        __syncthreads();
        if (wid == 0) {
            int x = (lane < 8) ? sscan[lane] : 0;
            #pragma unroll
            for (int o = 1; o < 8; o <<= 1) {
                int n = __shfl_up_sync(0xffffffffu, x, o);
                if (lane >= o) x += n;
            }
            if (lane < 8) sscan[lane] = x;
            if (lane == 7) stot = x;
        }
        __syncthreads();
        if (t < 256) {
            int P = incl + (wid ? sscan[wid-1] : 0);
            int total = stot;
            int above = total - P;            // elements in strictly higher bins
            if (above < Krem && Krem <= above + c) {
                sinfo[0] = t;
                sinfo[1] = Krem - above;
            }
        }
        __syncthreads();
        prefix |= ((unsigned)sinfo[0]) << shift;
        mask   |= 0xFFu << shift;
        Krem = sinfo[1];
        __syncthreads();
    }
    unsigned T = prefix;
    int R = Krem;

    // stable compaction: thread owns elements [8t, 8t+8)
    int base = t * 8;
    int eqc = 0;
    #pragma unroll
    for (int i = 0; i < 8; i++) eqc += (skey[base+i] == T);
    int tot;
    int eqoff = exscan512(eqc, sscan, &tot);

    int kc = 0;
    unsigned kmask = 0;
    int er = eqoff;
    #pragma unroll
    for (int i = 0; i < 8; i++) {
        unsigned u = skey[base+i];
        bool eq = (u == T);
        bool kp = (u > T) || (eq && er < R);
        er += eq;
        if (base + i == 0) kp = true;
        kmask |= (unsigned)kp << i;
        kc += kp;
    }
    int koff = exscan512(kc, sscan, &tot);
    int p = koff;
    #pragma unroll
    for (int i = 0; i < 8; i++) {
        if ((kmask >> i) & 1) g_sel[b*(TOPK_+1) + p++] = base + i;
    }
    if (t == 0) g_nsel[b] = tot;
}

// ---------------- kernel 4: attention ----------------
#define KTROWS 128   // keys per tile
#define KPAD   132   // padded row length (floats) for one 128-d chunk
#define SCPAD  648

struct AttnSmem {
    float q[16][ND_];            // 32 KB
    float k[2][KTROWS][KPAD];    // 132 KB double buffered k tiles
    float sc[16][SCPAD];         // 40.5 KB scores/probs (up to 640 cols)
    ull   kptr[640];             // 5 KB row base pointers
    float inv[16];
};

extern __shared__ char smem_raw[];

__device__ __forceinline__ void prefetch_stage(AttnSmem& S, int buf, int s,
                                               int nsel, int t) {
    int ch = s & 3, kbase = (s >> 2) << 7;
    #pragma unroll
    for (int i = 0; i < 16; i++) {
        int seg = t + (i << 8);
        int r = seg >> 5, c = seg & 31;
        int j = kbase + r;
        const char* src;
        int sz;
        if (j < nsel) { src = (const char*)S.kptr[j] + ch*512 + c*16; sz = 16; }
        else          { src = (const char*)g_qr; sz = 0; }
        cpa16(&S.k[buf][r][c*4], src, sz);
    }
    CP_COMMIT();
}

__global__ void __launch_bounds__(256, 1)
attn_kernel(const float* __restrict__ kv,
            const float* __restrict__ attn_sink,
            const int* __restrict__ btbl,
            float* __restrict__ out) {
    AttnSmem& S = *(AttnSmem*)smem_raw;
    int b = blockIdx.y, hg = blockIdx.x;
    int t = threadIdx.x;
    int nsel = g_nsel[b];
    int hbase = hg * 16;
    int ntile = (nsel + 127) >> 7;
    int nstage = ntile * 4;

    int hq = (t >> 6) << 2;    // 4 heads per thread, warp-uniform
    int kx = t & 63;           // key lane (keys kx, kx+64 of tile)
    int pd = t & 63;           // d-pair lane for phase C

    // load q (16 rows contiguous)
    {
        const float* qr = g_qr + ((size_t)b*NH_ + hbase) * ND_;
        for (int i = t*4; i < 16*ND_; i += 1024)
            *(float4*)&S.q[0][i] = *(const float4*)(qr + i);
    }
    // precompute row pointers
    for (int j = t; j < 640; j += 256) {
        const float* p = kv;
        if (j < nsel) {
            int sp = g_sel[b*(TOPK_+1) + j];
            int pg = btbl[(b << 6) + (sp >> 6)];
            p = kv + ((size_t)pg*BS_ + (sp & 63)) * ND_;
        }
        S.kptr[j] = (ull)p;
    }
    __syncthreads();

    float snk[4];
    #pragma unroll
    for (int h = 0; h < 4; h++) snk[h] = attn_sink[hbase + hq + h];

    // ======== phase A: scores ========
    ull accA[4][2];
    prefetch_stage(S, 0, 0, nsel, t);
    for (int s = 0; s < nstage; s++) {
        int buf = s & 1;
        if (s + 1 < nstage) { prefetch_stage(S, buf ^ 1, s + 1, nsel, t); CP_WAIT1(); }
        else                { CP_WAIT0(); }
        __syncthreads();
        int ch = s & 3, tile = s >> 2;
        if (ch == 0) {
            #pragma unroll
            for (int h = 0; h < 4; h++) { accA[h][0] = 0ull; accA[h][1] = 0ull; }
        }
        const float* kb0 = &S.k[buf][kx][0];
        const float* kb1 = &S.k[buf][kx+64][0];
        #pragma unroll 8
        for (int d = 0; d < 128; d += 4) {
            ulonglong2 ka = *(const ulonglong2*)(kb0 + d);
            ulonglong2 kc = *(const ulonglong2*)(kb1 + d);
            #pragma unroll
            for (int h = 0; h < 4; h++) {
                ulonglong2 qa = *(const ulonglong2*)&S.q[hq+h][ch*128 + d];
                FMA2(accA[h][0], qa.x, ka.x, accA[h][0]);
                FMA2(accA[h][0], qa.y, ka.y, accA[h][0]);
                FMA2(accA[h][1], qa.x, kc.x, accA[h][1]);
                FMA2(accA[h][1], qa.y, kc.y, accA[h][1]);
            }
        }
        if (ch == 3) {
            int j0 = (tile << 7) + kx, j1 = j0 + 64;
            #pragma unroll
            for (int h = 0; h < 4; h++) {
                float2 u0 = unpack2(accA[h][0]);
                float2 u1 = unpack2(accA[h][1]);
                float s0 = (u0.x + u0.y) * SCALE_;
                float s1 = (u1.x + u1.y) * SCALE_;
                if (j0 == 0) s0 += snk[h];
                if (j0 < nsel) S.sc[hq+h][j0] = s0;
                if (j1 < nsel) S.sc[hq+h][j1] = s1;
            }
        }
        __syncthreads();
    }

    // kick off phase C stage 0 prefetch (overlaps softmax)
    prefetch_stage(S, 0, 0, nsel, t);

    // ======== softmax (warp per 2 heads) ========
    {
        int wrp = t >> 5, jt = t & 31;
        #pragma unroll
        for (int hh = 0; hh < 2; hh++) {
            int hloc = 2*wrp + hh;
            float m = -3.4e38f;
            for (int j = jt; j < nsel; j += 32) m = fmaxf(m, S.sc[hloc][j]);
            #pragma unroll
            for (int o = 16; o; o >>= 1) m = fmaxf(m, __shfl_xor_sync(0xffffffffu, m, o));
            float sum = 0.f;
            for (int j = jt; j < nsel; j += 32) {
                float e = expf(S.sc[hloc][j] - m);
                S.sc[hloc][j] = e;
                sum += e;
            }
            #pragma unroll
            for (int o = 16; o; o >>= 1) sum += __shfl_xor_sync(0xffffffffu, sum, o);
            if (jt == 0) S.inv[hloc] = 1.f / sum;
        }
        // zero-pad probs for j in [nsel, ntile*128)
        int padhi = ntile << 7;
        for (int j = nsel + t; j < padhi; j += 256)
            #pragma unroll
            for (int h = 0; h < 16; h++) S.sc[h][j] = 0.f;
    }
    __syncthreads();

    // ======== phase C: output ========
    ull accC[4][4];
    #pragma unroll
    for (int h = 0; h < 4; h++)
        #pragma unroll
        for (int c = 0; c < 4; c++) accC[h][c] = 0ull;

    int dloc = pd * 2;
    for (int s = 0; s < nstage; s++) {
        int buf = s & 1;
        if (s + 1 < nstage) { prefetch_stage(S, buf ^ 1, s + 1, nsel, t); CP_WAIT1(); }
        else                { CP_WAIT0(); }
        __syncthreads();
        int ch = s & 3, kbase = (s >> 2) << 7;
        const float* pw0 = &S.sc[hq+0][kbase];
        const float* pw1 = &S.sc[hq+1][kbase];
        const float* pw2 = &S.sc[hq+2][kbase];
        const float* pw3 = &S.sc[hq+3][kbase];
        ull a0 = accC[0][ch], a1 = accC[1][ch], a2 = accC[2][ch], a3 = accC[3][ch];
        #pragma unroll 4
        for (int j = 0; j < 128; j += 4) {
            float4 w0 = *(const float4*)(pw0 + j);
            float4 w1 = *(const float4*)(pw1 + j);
            float4 w2 = *(const float4*)(pw2 + j);
            float4 w3 = *(const float4*)(pw3 + j);
            #pragma unroll
            for (int jj = 0; jj < 4; jj++) {
                ull kp = *(const ull*)&S.k[buf][j+jj][dloc];
                float f0 = (&w0.x)[jj], f1 = (&w1.x)[jj], f2 = (&w2.x)[jj], f3 = (&w3.x)[jj];
                FMA2(a0, dup2(f0), kp, a0);
                FMA2(a1, dup2(f1), kp, a1);
                FMA2(a2, dup2(f2), kp, a2);
                FMA2(a3, dup2(f3), kp, a3);
            }
        }
        accC[0][ch] = a0; accC[1][ch] = a1; accC[2][ch] = a2; accC[3][ch] = a3;
        __syncthreads();
    }

    // write output
    #pragma unroll
    for (int h = 0; h < 4; h++) {
        float iv = S.inv[hq + h];
        #pragma unroll
        for (int ch = 0; ch < 4; ch++) {
            float2 u = unpack2(accC[h][ch]);
            float2 o = make_float2(u.x * iv, u.y * iv);
            *(float2*)(out + ((size_t)b*NH_ + hbase + hq + h) * ND_ + ch*128 + dloc) = o;
        }
    }
}

// ---------------- launch ----------------
extern "C" void kernel_launch(void* const* d_in, const int* in_sizes, int n_in,
                              void* d_out, int out_size) {
    const float* q      = (const float*)d_in[0];
    const float* cosp   = (const float*)d_in[1];
    const float* sinp   = (const float*)d_in[2];
    const float* kv     = (const float*)d_in[3];
    const float* q_idx  = (const float*)d_in[4];
    const float* k_idx  = (const float*)d_in[5];
    const float* sink   = (const float*)d_in[6];
    const int*   btbl   = (const int*)d_in[7];
    const int*   slens  = (const int*)d_in[8];
    float* out = (float*)d_out;

    prep_kernel<<<1280, 256>>>(q, cosp, sinp, q_idx);
    indexer_kernel<<<dim3(16, NB_), 256>>>(k_idx, btbl, slens);
    topk_kernel<<<NB_, 512>>>();

    int smem = (int)sizeof(AttnSmem);
    cudaFuncSetAttribute(attn_kernel, cudaFuncAttributeMaxDynamicSharedMemorySize, smem);
    attn_kernel<<<dim3(4, NB_), 256, smem>>>(kv, sink, btbl, out);
}